// round 16
// baseline (speedup 1.0000x reference)
#include <cuda_runtime.h>

#define EDGES  1600000
#define NODES  50000
#define NGRAPH 16
#define KSLOT  8
#define HID    32
#define SCANB  ((NODES + 1023) / 1024)   // 49
#define AGGFLAG 0x40000000
#define AGGMASK 0x3FFFFFFF

// ---------------- static scratch (zero-initialized at module load) ----------------
__device__ int    g_ssed[EDGES];         // CSR-sorted src per edge
__device__ int    g_cnt[NODES];          // re-zeroed in k_scan
__device__ int    g_agg[64];             // lookback aggregates; re-zeroed in k_scatsrc
__device__ int    g_off[NODES + 1];
__device__ int    g_cur[NODES];
__device__ int    g_batch[NODES];
__device__ float4 g_pos4[NODES];         // padded pos rows (filled in k_scan)
__device__ float  g_XB[NODES * HID];     // 0.5 * (x[n] @ W1[4:8])
__device__ float  g_H[NODES * HID];
__device__ float  g_S[NODES * KSLOT];
__device__ float  g_POOL[NGRAPH * KSLOT * HID];  // zeroed in k_main block 0
__device__ float  g_Z[NGRAPH * KSLOT * 4];
__device__ unsigned g_poolcnt;           // re-zeroed by z block

// silu(a) = h + h*tanh(h), h = a/2 (single MUFU.TANH); callers pass h
__device__ __forceinline__ float silu_h(float h) {
    float t;
    asm("tanh.approx.f32 %0, %1;" : "=f"(t) : "f"(h));
    return fmaf(h, t, h);
}
__device__ __forceinline__ float siluf(float a) { return silu_h(a * 0.5f); }

__device__ __forceinline__ int detect64(const unsigned int* e) {
    int is64 = 1;
    for (int k = 1; k < 64; k += 2)
        if (e[k] != 0u) { is64 = 0; break; }
    return is64;
}

// ---------------- 1: dst histogram (reads dst half only) ----------------
__global__ void k_prep_a(const void* __restrict__ ei) {
    __shared__ int s64;
    if (threadIdx.x == 0) s64 = detect64((const unsigned int*)ei);
    __syncthreads();
    int is64 = s64;
    int base = (blockIdx.x * 128 + threadIdx.x) * 4;
    int4 dv;
    if (is64) {
        const longlong2* q = (const longlong2*)ei;
        longlong2 c = __ldg(q + ((EDGES + base) >> 1));
        longlong2 d = __ldg(q + ((EDGES + base) >> 1) + 1);
        dv = make_int4((int)c.x, (int)c.y, (int)d.x, (int)d.y);
    } else {
        dv = __ldg((const int4*)((const int*)ei + EDGES + base));
    }
    atomicAdd(&g_cnt[dv.x], 1);
    atomicAdd(&g_cnt[dv.y], 1);
    atomicAdd(&g_cnt[dv.z], 1);
    atomicAdd(&g_cnt[dv.w], 1);
}

// ---------------- 2: decoupled-lookback scan + batch convert + pos4 fill ----------------
__global__ void __launch_bounds__(1024) k_scan(const void* __restrict__ ei,
                                               const void* __restrict__ batch,
                                               const float* __restrict__ pos) {
    __shared__ int wsum[32];
    __shared__ int sbase;
    __shared__ int s64;
    if (threadIdx.x == 0) s64 = detect64((const unsigned int*)ei);
    int b = blockIdx.x;
    int n = b * 1024 + threadIdx.x;
    int lane = threadIdx.x & 31;
    int wid = threadIdx.x >> 5;
    int v = (n < NODES) ? g_cnt[n] : 0;
    int s = v;
#pragma unroll
    for (int o = 1; o < 32; o <<= 1) {
        int t = __shfl_up_sync(0xffffffffu, s, o);
        if (lane >= o) s += t;
    }
    if (lane == 31) wsum[wid] = s;
    __syncthreads();
    if (wid == 0) {
        int t = wsum[lane];
        int u = t;
#pragma unroll
        for (int o = 1; o < 32; o <<= 1) {
            int q = __shfl_up_sync(0xffffffffu, u, o);
            if (lane >= o) u += q;
        }
        wsum[lane] = u - t;
    }
    __syncthreads();
    int incl = s + wsum[wid];
    if (threadIdx.x == 1023)
        atomicExch(&g_agg[b], incl | AGGFLAG);
    if (wid == 0) {
        int sum = 0;
        for (int p = lane; p < b; p += 32) {
            int a;
            do { a = atomicAdd(&g_agg[p], 0); } while (!(a & AGGFLAG));
            sum += a & AGGMASK;
        }
#pragma unroll
        for (int o = 16; o; o >>= 1) sum += __shfl_xor_sync(0xffffffffu, sum, o);
        if (lane == 0) sbase = sum;
    }
    __syncthreads();
    if (n < NODES) {
        int off = sbase + incl - v;
        g_off[n] = off;
        g_cur[n] = off;
        g_cnt[n] = 0;                            // reset for next replay
        g_batch[n] = s64 ? (int)((const long long*)batch)[n]
                         : ((const int*)batch)[n];
        g_pos4[n] = make_float4(__ldg(pos + 3 * n), __ldg(pos + 3 * n + 1),
                                __ldg(pos + 3 * n + 2), 0.0f);
    }
    if (n == 0) g_off[NODES] = EDGES;
}

// ---------------- 3: scatter src into CSR order + XB precompute (4 edges/thread) ----------------
// grid 3125, block 128
__global__ void __launch_bounds__(128) k_scatsrc(const void* __restrict__ ei,
                                                 const float* __restrict__ x,
                                                 const float* __restrict__ w1) {
    __shared__ int s64;
    if (threadIdx.x == 0) s64 = detect64((const unsigned int*)ei);
    __syncthreads();
    int is64 = s64;
    int tid = blockIdx.x * 128 + threadIdx.x;
    int i0 = tid * 4;
    int4 sp, dp;
    if (is64) {
        const longlong2* q = (const longlong2*)ei;
        longlong2 a = __ldg(q + (i0 >> 1));
        longlong2 b = __ldg(q + (i0 >> 1) + 1);
        sp = make_int4((int)a.x, (int)a.y, (int)b.x, (int)b.y);
        longlong2 c = __ldg(q + ((EDGES + i0) >> 1));
        longlong2 d = __ldg(q + ((EDGES + i0) >> 1) + 1);
        dp = make_int4((int)c.x, (int)c.y, (int)d.x, (int)d.y);
    } else {
        sp = __ldg((const int4*)((const int*)ei + i0));
        dp = __ldg((const int4*)((const int*)ei + EDGES + i0));
    }
    int p0 = atomicAdd(&g_cur[dp.x], 1);
    int p1 = atomicAdd(&g_cur[dp.y], 1);
    int p2 = atomicAdd(&g_cur[dp.z], 1);
    int p3 = atomicAdd(&g_cur[dp.w], 1);
    g_ssed[p0] = sp.x;
    g_ssed[p1] = sp.y;
    g_ssed[p2] = sp.z;
    g_ssed[p3] = sp.w;

    {   // XB for flat indices i0..i0+3 (same node row; 4 adjacent columns), pre-halved
        int n = i0 >> 5, j = i0 & 31;               // j % 4 == 0
        float4 xv = __ldg((const float4*)(x + ((size_t)n << 2)));
        float4 w4 = __ldg((const float4*)(w1 + 4 * 32 + j));
        float4 w5 = __ldg((const float4*)(w1 + 5 * 32 + j));
        float4 w6 = __ldg((const float4*)(w1 + 6 * 32 + j));
        float4 w7 = __ldg((const float4*)(w1 + 7 * 32 + j));
        float4 a;
        a.x = fmaf(xv.w, w7.x, fmaf(xv.z, w6.x, fmaf(xv.y, w5.x, xv.x * w4.x))) * 0.5f;
        a.y = fmaf(xv.w, w7.y, fmaf(xv.z, w6.y, fmaf(xv.y, w5.y, xv.x * w4.y))) * 0.5f;
        a.z = fmaf(xv.w, w7.z, fmaf(xv.z, w6.z, fmaf(xv.y, w5.z, xv.x * w4.z))) * 0.5f;
        a.w = fmaf(xv.w, w7.w, fmaf(xv.z, w6.w, fmaf(xv.y, w5.w, xv.x * w4.w))) * 0.5f;
        *(float4*)(g_XB + i0) = a;
    }
    if (tid < 64) g_agg[tid] = 0;                // reset lookback flags
}

// ---------------- 4: main gather + lane-parallel dist + silu-mean + W2 + softmax ----------------
__global__ void __launch_bounds__(256, 8) k_main(const float* __restrict__ x,
                                                 const float* __restrict__ w1,
                                                 const float* __restrict__ b1,
                                                 const float* __restrict__ w2,
                                                 const float* __restrict__ b2,
                                                 const float* __restrict__ pw,
                                                 const float* __restrict__ pb) {
    __shared__ __align__(16) float sw2[HID * HID];
    __shared__ __align__(16) float spwt[KSLOT][36];  // transposed pw, bank-padded
    __shared__ float spb[KSLOT];
    __shared__ __align__(16) float sh[8][HID];
    __shared__ __align__(16) int2  sed_s[8][32];     // per-warp staged {src*32, dist}
    int t = threadIdx.x;
    if (blockIdx.x == 0)
        for (int i = t; i < NGRAPH * KSLOT * HID; i += 256) g_POOL[i] = 0.0f;
    for (int i = t; i < HID * HID; i += 256) sw2[i] = w2[i];
    if (t < HID * KSLOT) spwt[t & 7][t >> 3] = pw[t];    // spwt[k][j] = pw[j*8+k]
    if (t < KSLOT) spb[t] = pb[t];
    __syncthreads();

    int lane = t & 31;
    int w = t >> 5;

    float w1a0 = 0.5f * __ldg(w1 + 0 * 32 + lane);
    float w1a1 = 0.5f * __ldg(w1 + 1 * 32 + lane);
    float w1a2 = 0.5f * __ldg(w1 + 2 * 32 + lane);
    float w1a3 = 0.5f * __ldg(w1 + 3 * 32 + lane);
    float cw   = 0.5f * __ldg(w1 + 8 * 32 + lane);
    float b1r  = 0.5f * __ldg(b1 + lane);
    float b2r  = __ldg(b2 + lane);

    const float* xb_base = g_XB + lane;

    int gw = (blockIdx.x << 3) + w;
    int nwarp = gridDim.x << 3;

    for (int node = gw; node < NODES; node += nwarp) {
        int beg = g_off[node];
        int end = g_off[node + 1];
        float4 xd = __ldg((const float4*)(x + ((size_t)node << 2)));
        float base = b1r;
        base = fmaf(xd.x, w1a0, base);
        base = fmaf(xd.y, w1a1, base);
        base = fmaf(xd.z, w1a2, base);
        base = fmaf(xd.w, w1a3, base);
        float4 pn = __ldg(&g_pos4[node]);

        float acc0 = 0.0f, acc1 = 0.0f;
        for (int i = beg; i < end; i += 32) {
            int rem = end - i;
            int take = rem < 32 ? rem : 32;
            int li = (lane < take) ? lane : 0;
            int srcv = __ldg(g_ssed + i + li);        // coalesced
            float4 p = __ldg(&g_pos4[srcv]);          // lane-scattered gather
            float dx = p.x - pn.x, dy = p.y - pn.y, dz = p.z - pn.z;
            float dist = sqrtf(fmaf(dx, dx, fmaf(dy, dy, dz * dz)));
            sed_s[w][lane] = make_int2(srcv << 5, __float_as_int(dist));
            __syncwarp();
            if (take == 32) {
#pragma unroll
                for (int kb = 0; kb < 32; kb += 8) {
                    int4 E[4];
                    float xb[8];
#pragma unroll
                    for (int u = 0; u < 4; u++)
                        E[u] = *(const int4*)&sed_s[w][kb + 2 * u];   // LDS.128 bcast (2 edges)
#pragma unroll
                    for (int u = 0; u < 4; u++) {
                        xb[2 * u]     = __ldg(xb_base + E[u].x);
                        xb[2 * u + 1] = __ldg(xb_base + E[u].z);
                    }
#pragma unroll
                    for (int u = 0; u < 4; u++) {
                        float h0 = fmaf(__int_as_float(E[u].y), cw, base) + xb[2 * u];
                        float h1 = fmaf(__int_as_float(E[u].w), cw, base) + xb[2 * u + 1];
                        acc0 += silu_h(h0);
                        acc1 += silu_h(h1);
                    }
                }
            } else {
                for (int k = 0; k < take; k++) {
                    int2 e = sed_s[w][k];
                    float xb = __ldg(xb_base + e.x);
                    float h = fmaf(__int_as_float(e.y), cw, base) + xb;
                    acc0 += silu_h(h);
                }
            }
            __syncwarp();
        }

        int deg = end - beg;
        float inv = (deg > 0) ? __fdividef(1.0f, (float)deg) : 0.0f;
        float hsil = (acc0 + acc1) * inv;

        sh[w][lane] = hsil;
        __syncwarp();
        float h = (deg > 0) ? b2r : 0.0f;
#pragma unroll
        for (int j4 = 0; j4 < 32; j4 += 4) {
            float4 hv = *(const float4*)&sh[w][j4];   // LDS.128 bcast
            h = fmaf(hv.x, sw2[(j4 + 0) * 32 + lane], h);
            h = fmaf(hv.y, sw2[(j4 + 1) * 32 + lane], h);
            h = fmaf(hv.z, sw2[(j4 + 2) * 32 + lane], h);
            h = fmaf(hv.w, sw2[(j4 + 3) * 32 + lane], h);
        }
        __syncwarp();

        g_H[((size_t)node << 5) + lane] = h;
        sh[w][lane] = h;
        __syncwarp();

        if (lane < 8) {
            float l = spb[lane];
#pragma unroll
            for (int j4 = 0; j4 < 32; j4 += 4) {
                float4 hv = *(const float4*)&sh[w][j4];      // bcast
                float4 wv = *(const float4*)&spwt[lane][j4]; // conflict-free per-lane row
                l = fmaf(hv.x, wv.x, l);
                l = fmaf(hv.y, wv.y, l);
                l = fmaf(hv.z, wv.z, l);
                l = fmaf(hv.w, wv.w, l);
            }
            float m = l;
            m = fmaxf(m, __shfl_xor_sync(0xff, m, 4, 8));
            m = fmaxf(m, __shfl_xor_sync(0xff, m, 2, 8));
            m = fmaxf(m, __shfl_xor_sync(0xff, m, 1, 8));
            float ex = __expf(l - m);
            float sum = ex;
            sum += __shfl_xor_sync(0xff, sum, 4, 8);
            sum += __shfl_xor_sync(0xff, sum, 2, 8);
            sum += __shfl_xor_sync(0xff, sum, 1, 8);
            g_S[((size_t)node << 3) + lane] = __fdividef(ex, sum);
        }
        __syncwarp();
    }
}

// ---------------- 5: pooling (512 blocks) + fused z in last block ----------------
__global__ void __launch_bounds__(256) k_pool(const float* __restrict__ tw,
                                              const float* __restrict__ tb) {
    int b = blockIdx.x & 15;
    int slice = blockIdx.x >> 4;                 // 0..31

    int lo = 0, hi = NODES;
    while (lo < hi) { int m = (lo + hi) >> 1; if (g_batch[m] < b) lo = m + 1; else hi = m; }
    int start = lo;
    lo = start; hi = NODES;
    while (lo < hi) { int m = (lo + hi) >> 1; if (g_batch[m] < b + 1) lo = m + 1; else hi = m; }
    int end = lo;

    int cnt = end - start;
    int s0 = start + (cnt * slice) / 32;
    int s1 = start + (cnt * (slice + 1)) / 32;

    int k = threadIdx.x >> 5;
    int j = threadIdx.x & 31;

    float acc = 0.0f;
#pragma unroll 8
    for (int n = s0; n < s1; n++)
        acc = fmaf(__ldg(g_S + (size_t)n * KSLOT + k), __ldg(g_H + (size_t)n * HID + j), acc);

    atomicAdd(&g_POOL[(b * KSLOT + k) * HID + j], acc);
    __threadfence();

    __shared__ unsigned slast;
    if (threadIdx.x == 0) slast = atomicAdd(&g_poolcnt, 1u);
    __syncthreads();
    if (slast == 511) {                          // last block computes z
        for (int it = threadIdx.x; it < NGRAPH * KSLOT * 4; it += 256) {
            int bb = it >> 5;
            int kk = (it >> 2) & 7;
            int dd = it & 3;
            float acc2 = __ldg(tb + dd);
#pragma unroll
            for (int jj = 0; jj < HID; jj++)
                acc2 = fmaf(__ldcg(&g_POOL[bb * 256 + kk * 32 + jj]),
                            __ldg(tw + jj * 4 + dd), acc2);
            g_Z[it] = acc2;
        }
        if (threadIdx.x == 0) g_poolcnt = 0;
    }
}

// ---------------- 6: decode ----------------
__global__ void __launch_bounds__(128) k_dec(const float* __restrict__ w1,
                                             const float* __restrict__ b1,
                                             const float* __restrict__ w2,
                                             const float* __restrict__ b2,
                                             float* __restrict__ out) {
    __shared__ __align__(16) float sz[NGRAPH * KSLOT * 4];
    __shared__ __align__(16) float sw1[128];
    __shared__ float sb1[32];
    __shared__ __align__(16) float sw2[128];
    __shared__ float sb2v[4];

    int t = threadIdx.x;
    for (int i = t; i < 512; i += 128) sz[i] = g_Z[i];
    sw1[t] = w1[(t & 3) * 32 + (t >> 2)];
    sw2[t] = w2[t];
    if (t < 32) sb1[t] = b1[t];
    if (t < 4)  sb2v[t] = b2[t];
    __syncthreads();

    int n = blockIdx.x * 128 + t;
    if (n >= NODES) return;

    float4 sa = *(const float4*)(g_S + (size_t)n * KSLOT);
    float4 sbv = *(const float4*)(g_S + (size_t)n * KSLOT + 4);
    float s[8] = { sa.x, sa.y, sa.z, sa.w, sbv.x, sbv.y, sbv.z, sbv.w };

#pragma unroll 1
    for (int b = 0; b < NGRAPH; b++) {
        float q0 = 0.f, q1 = 0.f, q2 = 0.f, q3 = 0.f;
#pragma unroll
        for (int k = 0; k < 8; k++) {
            float4 zv = *(const float4*)&sz[(b * 8 + k) * 4];
            q0 = fmaf(s[k], zv.x, q0);
            q1 = fmaf(s[k], zv.y, q1);
            q2 = fmaf(s[k], zv.z, q2);
            q3 = fmaf(s[k], zv.w, q3);
        }
        float o0 = sb2v[0], o1 = sb2v[1], o2 = sb2v[2], o3 = sb2v[3];
#pragma unroll
        for (int j = 0; j < 32; j++) {
            float4 wc = *(const float4*)&sw1[j * 4];
            float tt = sb1[j];
            tt = fmaf(q0, wc.x, tt);
            tt = fmaf(q1, wc.y, tt);
            tt = fmaf(q2, wc.z, tt);
            tt = fmaf(q3, wc.w, tt);
            tt = siluf(tt);
            float4 wr = *(const float4*)&sw2[j * 4];
            o0 = fmaf(tt, wr.x, o0);
            o1 = fmaf(tt, wr.y, o1);
            o2 = fmaf(tt, wr.z, o2);
            o3 = fmaf(tt, wr.w, o3);
        }
        *(float4*)(out + ((size_t)b * NODES + n) * 4) = make_float4(o0, o1, o2, o3);
    }
}

// ---------------- launch ----------------
extern "C" void kernel_launch(void* const* d_in, const int* in_sizes, int n_in,
                              void* d_out, int out_size) {
    const float* x      = (const float*)d_in[0];
    const float* pos    = (const float*)d_in[1];
    const void*  ei     = d_in[2];
    const void*  batch  = d_in[3];
    const float* enc_w1 = (const float*)d_in[4];
    const float* enc_b1 = (const float*)d_in[5];
    const float* enc_w2 = (const float*)d_in[6];
    const float* enc_b2 = (const float*)d_in[7];
    const float* pool_w = (const float*)d_in[8];
    const float* pool_b = (const float*)d_in[9];
    const float* toz_w  = (const float*)d_in[10];
    const float* toz_b  = (const float*)d_in[11];
    const float* dec_w1 = (const float*)d_in[12];
    const float* dec_b1 = (const float*)d_in[13];
    const float* dec_w2 = (const float*)d_in[14];
    const float* dec_b2 = (const float*)d_in[15];
    float* out = (float*)d_out;

    k_prep_a<<<3125, 128>>>(ei);                             // 1
    k_scan<<<SCANB, 1024>>>(ei, batch, pos);                 // 2 (+batch+pos4)
    k_scatsrc<<<3125, 128>>>(ei, x, enc_w1);                 // 3 (4 edges/thread)
    k_main<<<1184, 256>>>(x, enc_w1, enc_b1, enc_w2, enc_b2, // 4  <- profiled slot
                          pool_w, pool_b);
    k_pool<<<512, 256>>>(toz_w, toz_b);                      // 5 (+fused z)
    k_dec<<<(NODES + 127) / 128, 128>>>(dec_w1, dec_b1, dec_w2, dec_b2, out);  // 6
}

// round 17
// speedup vs baseline: 1.0326x; 1.0326x over previous
#include <cuda_runtime.h>

#define EDGES  1600000
#define NODES  50000
#define NGRAPH 16
#define KSLOT  8
#define HID    32
#define SCANB  ((NODES + 1023) / 1024)   // 49
#define AGGFLAG 0x40000000
#define AGGMASK 0x3FFFFFFF

// ---------------- static scratch (zero-initialized at module load) ----------------
__device__ int    g_ssed[EDGES];         // CSR-sorted src per edge
__device__ int    g_cnt[NODES];          // re-zeroed in k_scan
__device__ int    g_agg[64];             // lookback aggregates; re-zeroed in k_scatsrc
__device__ int    g_off[NODES + 1];
__device__ int    g_cur[NODES];
__device__ int    g_batch[NODES];
__device__ float4 g_pos4[NODES];         // padded pos rows (filled in k_scan)
__device__ float  g_XB[NODES * HID];     // 0.5 * (x[n] @ W1[4:8])
__device__ float  g_H[NODES * HID];
__device__ float  g_S[NODES * KSLOT];
__device__ float  g_POOL[NGRAPH * KSLOT * HID];  // zeroed in k_main block 0
__device__ float  g_Z[NGRAPH * KSLOT * 4];
__device__ unsigned g_poolcnt;           // re-zeroed by z block

// silu(a) = h + h*tanh(h), h = a/2 (single MUFU.TANH); callers pass h
__device__ __forceinline__ float silu_h(float h) {
    float t;
    asm("tanh.approx.f32 %0, %1;" : "=f"(t) : "f"(h));
    return fmaf(h, t, h);
}
__device__ __forceinline__ float siluf(float a) { return silu_h(a * 0.5f); }

__device__ __forceinline__ int detect64(const unsigned int* e) {
    int is64 = 1;
    for (int k = 1; k < 64; k += 2)
        if (e[k] != 0u) { is64 = 0; break; }
    return is64;
}

// ---------------- 1: dst histogram (reads dst half only) ----------------
__global__ void k_prep_a(const void* __restrict__ ei) {
    __shared__ int s64;
    if (threadIdx.x == 0) s64 = detect64((const unsigned int*)ei);
    __syncthreads();
    int is64 = s64;
    int base = (blockIdx.x * 128 + threadIdx.x) * 4;
    int4 dv;
    if (is64) {
        const longlong2* q = (const longlong2*)ei;
        longlong2 c = __ldg(q + ((EDGES + base) >> 1));
        longlong2 d = __ldg(q + ((EDGES + base) >> 1) + 1);
        dv = make_int4((int)c.x, (int)c.y, (int)d.x, (int)d.y);
    } else {
        dv = __ldg((const int4*)((const int*)ei + EDGES + base));
    }
    atomicAdd(&g_cnt[dv.x], 1);
    atomicAdd(&g_cnt[dv.y], 1);
    atomicAdd(&g_cnt[dv.z], 1);
    atomicAdd(&g_cnt[dv.w], 1);
}

// ---------------- 2: decoupled-lookback scan + batch convert + pos4 fill ----------------
__global__ void __launch_bounds__(1024) k_scan(const void* __restrict__ ei,
                                               const void* __restrict__ batch,
                                               const float* __restrict__ pos) {
    __shared__ int wsum[32];
    __shared__ int sbase;
    __shared__ int s64;
    if (threadIdx.x == 0) s64 = detect64((const unsigned int*)ei);
    int b = blockIdx.x;
    int n = b * 1024 + threadIdx.x;
    int lane = threadIdx.x & 31;
    int wid = threadIdx.x >> 5;
    int v = (n < NODES) ? g_cnt[n] : 0;
    int s = v;
#pragma unroll
    for (int o = 1; o < 32; o <<= 1) {
        int t = __shfl_up_sync(0xffffffffu, s, o);
        if (lane >= o) s += t;
    }
    if (lane == 31) wsum[wid] = s;
    __syncthreads();
    if (wid == 0) {
        int t = wsum[lane];
        int u = t;
#pragma unroll
        for (int o = 1; o < 32; o <<= 1) {
            int q = __shfl_up_sync(0xffffffffu, u, o);
            if (lane >= o) u += q;
        }
        wsum[lane] = u - t;
    }
    __syncthreads();
    int incl = s + wsum[wid];
    if (threadIdx.x == 1023)
        atomicExch(&g_agg[b], incl | AGGFLAG);
    if (wid == 0) {
        int sum = 0;
        for (int p = lane; p < b; p += 32) {
            int a;
            do { a = atomicAdd(&g_agg[p], 0); } while (!(a & AGGFLAG));
            sum += a & AGGMASK;
        }
#pragma unroll
        for (int o = 16; o; o >>= 1) sum += __shfl_xor_sync(0xffffffffu, sum, o);
        if (lane == 0) sbase = sum;
    }
    __syncthreads();
    if (n < NODES) {
        int off = sbase + incl - v;
        g_off[n] = off;
        g_cur[n] = off;
        g_cnt[n] = 0;                            // reset for next replay
        g_batch[n] = s64 ? (int)((const long long*)batch)[n]
                         : ((const int*)batch)[n];
        g_pos4[n] = make_float4(__ldg(pos + 3 * n), __ldg(pos + 3 * n + 1),
                                __ldg(pos + 3 * n + 2), 0.0f);
    }
    if (n == 0) g_off[NODES] = EDGES;
}

// ---------------- 3: scatter src into CSR order + XB precompute (2 edges/thread) ----------------
__global__ void __launch_bounds__(256) k_scatsrc(const void* __restrict__ ei,
                                                 const float* __restrict__ x,
                                                 const float* __restrict__ w1) {
    __shared__ int s64;
    if (threadIdx.x == 0) s64 = detect64((const unsigned int*)ei);
    __syncthreads();
    int is64 = s64;
    int tid = blockIdx.x * 256 + threadIdx.x;
    int i0 = tid * 2;
    int2 sp, dp;
    if (is64) {
        const longlong2* q = (const longlong2*)ei;
        longlong2 a = __ldg(q + (i0 >> 1));
        longlong2 c = __ldg(q + ((EDGES + i0) >> 1));
        sp = make_int2((int)a.x, (int)a.y);
        dp = make_int2((int)c.x, (int)c.y);
    } else {
        sp = __ldg((const int2*)((const int*)ei + i0));
        dp = __ldg((const int2*)((const int*)ei + EDGES + i0));
    }
    int p0 = atomicAdd(&g_cur[dp.x], 1);
    int p1 = atomicAdd(&g_cur[dp.y], 1);
    g_ssed[p0] = sp.x;
    g_ssed[p1] = sp.y;

    {   // XB for flat indices i0, i0+1 (same node row; adjacent columns), pre-halved
        int n = i0 >> 5, j = i0 & 31;
        float4 xv = __ldg((const float4*)(x + ((size_t)n << 2)));
        float a0 = xv.x * __ldg(w1 + 4 * 32 + j);
        float a1 = xv.x * __ldg(w1 + 4 * 32 + j + 1);
        a0 = fmaf(xv.y, __ldg(w1 + 5 * 32 + j),     a0);
        a1 = fmaf(xv.y, __ldg(w1 + 5 * 32 + j + 1), a1);
        a0 = fmaf(xv.z, __ldg(w1 + 6 * 32 + j),     a0);
        a1 = fmaf(xv.z, __ldg(w1 + 6 * 32 + j + 1), a1);
        a0 = fmaf(xv.w, __ldg(w1 + 7 * 32 + j),     a0);
        a1 = fmaf(xv.w, __ldg(w1 + 7 * 32 + j + 1), a1);
        *(float2*)(g_XB + i0) = make_float2(a0 * 0.5f, a1 * 0.5f);
    }
    if (tid < 64) g_agg[tid] = 0;                // reset lookback flags
}

// ---------------- 4: main gather (double-buffered pipeline) + silu-mean + W2 + softmax ----------------
__global__ void __launch_bounds__(256, 8) k_main(const float* __restrict__ x,
                                                 const float* __restrict__ w1,
                                                 const float* __restrict__ b1,
                                                 const float* __restrict__ w2,
                                                 const float* __restrict__ b2,
                                                 const float* __restrict__ pw,
                                                 const float* __restrict__ pb) {
    __shared__ __align__(16) float sw2[HID * HID];
    __shared__ __align__(16) float spwt[KSLOT][36];  // transposed pw, bank-padded
    __shared__ float spb[KSLOT];
    __shared__ __align__(16) float sh[8][HID];
    __shared__ __align__(16) int2  sed_s[8][2][32];  // per-warp double-buffered staging
    int t = threadIdx.x;
    if (blockIdx.x == 0)
        for (int i = t; i < NGRAPH * KSLOT * HID; i += 256) g_POOL[i] = 0.0f;
    for (int i = t; i < HID * HID; i += 256) sw2[i] = w2[i];
    if (t < HID * KSLOT) spwt[t & 7][t >> 3] = pw[t];    // spwt[k][j] = pw[j*8+k]
    if (t < KSLOT) spb[t] = pb[t];
    __syncthreads();

    int lane = t & 31;
    int w = t >> 5;

    float w1a0 = 0.5f * __ldg(w1 + 0 * 32 + lane);
    float w1a1 = 0.5f * __ldg(w1 + 1 * 32 + lane);
    float w1a2 = 0.5f * __ldg(w1 + 2 * 32 + lane);
    float w1a3 = 0.5f * __ldg(w1 + 3 * 32 + lane);
    float cw   = 0.5f * __ldg(w1 + 8 * 32 + lane);
    float b1r  = 0.5f * __ldg(b1 + lane);
    float b2r  = __ldg(b2 + lane);

    const float* xb_base = g_XB + lane;

    int gw = (blockIdx.x << 3) + w;
    int nwarp = gridDim.x << 3;

    for (int node = gw; node < NODES; node += nwarp) {
        int beg = g_off[node];
        int end = g_off[node + 1];
        float4 xd = __ldg((const float4*)(x + ((size_t)node << 2)));
        float base = b1r;
        base = fmaf(xd.x, w1a0, base);
        base = fmaf(xd.y, w1a1, base);
        base = fmaf(xd.z, w1a2, base);
        base = fmaf(xd.w, w1a3, base);
        float4 pn = __ldg(&g_pos4[node]);

        float acc0 = 0.0f, acc1 = 0.0f;
        if (beg < end) {
            // prologue: stage batch 0
            {
                int take = end - beg; if (take > 32) take = 32;
                int li = (lane < take) ? lane : 0;
                int srcv = __ldg(g_ssed + beg + li);
                float4 p = __ldg(&g_pos4[srcv]);
                float dx = p.x - pn.x, dy = p.y - pn.y, dz = p.z - pn.z;
                float dist = sqrtf(fmaf(dx, dx, fmaf(dy, dy, dz * dz)));
                sed_s[w][0][lane] = make_int2(srcv << 5, __float_as_int(dist));
            }
            int buf = 0;
            for (int i = beg; i < end; i += 32, buf ^= 1) {
                __syncwarp();
                int ni = i + 32;
                if (ni < end) {                       // prefetch + stage next batch
                    int ntake = end - ni; if (ntake > 32) ntake = 32;
                    int nli = (lane < ntake) ? lane : 0;
                    int nsrc = __ldg(g_ssed + ni + nli);
                    float4 np = __ldg(&g_pos4[nsrc]);
                    float dx = np.x - pn.x, dy = np.y - pn.y, dz = np.z - pn.z;
                    float nd = sqrtf(fmaf(dx, dx, fmaf(dy, dy, dz * dz)));
                    sed_s[w][buf ^ 1][lane] = make_int2(nsrc << 5, __float_as_int(nd));
                }
                int take = end - i; if (take > 32) take = 32;
                if (take == 32) {
#pragma unroll
                    for (int kb = 0; kb < 32; kb += 8) {
                        int4 E[4];
                        float xb[8];
#pragma unroll
                        for (int u = 0; u < 4; u++)
                            E[u] = *(const int4*)&sed_s[w][buf][kb + 2 * u];  // LDS.128 bcast
#pragma unroll
                        for (int u = 0; u < 4; u++) {
                            xb[2 * u]     = __ldg(xb_base + E[u].x);
                            xb[2 * u + 1] = __ldg(xb_base + E[u].z);
                        }
#pragma unroll
                        for (int u = 0; u < 4; u++) {
                            float h0 = fmaf(__int_as_float(E[u].y), cw, base) + xb[2 * u];
                            float h1 = fmaf(__int_as_float(E[u].w), cw, base) + xb[2 * u + 1];
                            acc0 += silu_h(h0);
                            acc1 += silu_h(h1);
                        }
                    }
                } else {
                    for (int k = 0; k < take; k++) {
                        int2 e = sed_s[w][buf][k];
                        float xb = __ldg(xb_base + e.x);
                        float h = fmaf(__int_as_float(e.y), cw, base) + xb;
                        acc0 += silu_h(h);
                    }
                }
            }
            __syncwarp();
        }

        int deg = end - beg;
        float inv = (deg > 0) ? __fdividef(1.0f, (float)deg) : 0.0f;
        float hsil = (acc0 + acc1) * inv;

        sh[w][lane] = hsil;
        __syncwarp();
        float h = (deg > 0) ? b2r : 0.0f;
#pragma unroll
        for (int j4 = 0; j4 < 32; j4 += 4) {
            float4 hv = *(const float4*)&sh[w][j4];   // LDS.128 bcast
            h = fmaf(hv.x, sw2[(j4 + 0) * 32 + lane], h);
            h = fmaf(hv.y, sw2[(j4 + 1) * 32 + lane], h);
            h = fmaf(hv.z, sw2[(j4 + 2) * 32 + lane], h);
            h = fmaf(hv.w, sw2[(j4 + 3) * 32 + lane], h);
        }
        __syncwarp();

        g_H[((size_t)node << 5) + lane] = h;
        sh[w][lane] = h;
        __syncwarp();

        if (lane < 8) {
            float l = spb[lane];
#pragma unroll
            for (int j4 = 0; j4 < 32; j4 += 4) {
                float4 hv = *(const float4*)&sh[w][j4];      // bcast
                float4 wv = *(const float4*)&spwt[lane][j4]; // conflict-free per-lane row
                l = fmaf(hv.x, wv.x, l);
                l = fmaf(hv.y, wv.y, l);
                l = fmaf(hv.z, wv.z, l);
                l = fmaf(hv.w, wv.w, l);
            }
            float m = l;
            m = fmaxf(m, __shfl_xor_sync(0xff, m, 4, 8));
            m = fmaxf(m, __shfl_xor_sync(0xff, m, 2, 8));
            m = fmaxf(m, __shfl_xor_sync(0xff, m, 1, 8));
            float ex = __expf(l - m);
            float sum = ex;
            sum += __shfl_xor_sync(0xff, sum, 4, 8);
            sum += __shfl_xor_sync(0xff, sum, 2, 8);
            sum += __shfl_xor_sync(0xff, sum, 1, 8);
            g_S[((size_t)node << 3) + lane] = __fdividef(ex, sum);
        }
        __syncwarp();
    }
}

// ---------------- 5: pooling (256 blocks) + fused z in last block ----------------
__global__ void __launch_bounds__(256) k_pool(const float* __restrict__ tw,
                                              const float* __restrict__ tb) {
    int b = blockIdx.x & 15;
    int slice = blockIdx.x >> 4;

    int lo = 0, hi = NODES;
    while (lo < hi) { int m = (lo + hi) >> 1; if (g_batch[m] < b) lo = m + 1; else hi = m; }
    int start = lo;
    lo = start; hi = NODES;
    while (lo < hi) { int m = (lo + hi) >> 1; if (g_batch[m] < b + 1) lo = m + 1; else hi = m; }
    int end = lo;

    int cnt = end - start;
    int s0 = start + (cnt * slice) / 16;
    int s1 = start + (cnt * (slice + 1)) / 16;

    int k = threadIdx.x >> 5;
    int j = threadIdx.x & 31;

    float acc = 0.0f;
#pragma unroll 8
    for (int n = s0; n < s1; n++)
        acc = fmaf(__ldg(g_S + (size_t)n * KSLOT + k), __ldg(g_H + (size_t)n * HID + j), acc);

    atomicAdd(&g_POOL[(b * KSLOT + k) * HID + j], acc);
    __threadfence();

    __shared__ unsigned slast;
    if (threadIdx.x == 0) slast = atomicAdd(&g_poolcnt, 1u);
    __syncthreads();
    if (slast == 255) {                          // last block computes z
        for (int it = threadIdx.x; it < NGRAPH * KSLOT * 4; it += 256) {
            int bb = it >> 5;
            int kk = (it >> 2) & 7;
            int dd = it & 3;
            float acc2 = __ldg(tb + dd);
#pragma unroll
            for (int jj = 0; jj < HID; jj++)
                acc2 = fmaf(__ldcg(&g_POOL[bb * 256 + kk * 32 + jj]),
                            __ldg(tw + jj * 4 + dd), acc2);
            g_Z[it] = acc2;
        }
        if (threadIdx.x == 0) g_poolcnt = 0;
    }
}

// ---------------- 6: decode ----------------
__global__ void __launch_bounds__(128) k_dec(const float* __restrict__ w1,
                                             const float* __restrict__ b1,
                                             const float* __restrict__ w2,
                                             const float* __restrict__ b2,
                                             float* __restrict__ out) {
    __shared__ __align__(16) float sz[NGRAPH * KSLOT * 4];
    __shared__ __align__(16) float sw1[128];
    __shared__ float sb1[32];
    __shared__ __align__(16) float sw2[128];
    __shared__ float sb2v[4];

    int t = threadIdx.x;
    for (int i = t; i < 512; i += 128) sz[i] = g_Z[i];
    sw1[t] = w1[(t & 3) * 32 + (t >> 2)];
    sw2[t] = w2[t];
    if (t < 32) sb1[t] = b1[t];
    if (t < 4)  sb2v[t] = b2[t];
    __syncthreads();

    int n = blockIdx.x * 128 + t;
    if (n >= NODES) return;

    float4 sa = *(const float4*)(g_S + (size_t)n * KSLOT);
    float4 sbv = *(const float4*)(g_S + (size_t)n * KSLOT + 4);
    float s[8] = { sa.x, sa.y, sa.z, sa.w, sbv.x, sbv.y, sbv.z, sbv.w };

#pragma unroll 1
    for (int b = 0; b < NGRAPH; b++) {
        float q0 = 0.f, q1 = 0.f, q2 = 0.f, q3 = 0.f;
#pragma unroll
        for (int k = 0; k < 8; k++) {
            float4 zv = *(const float4*)&sz[(b * 8 + k) * 4];
            q0 = fmaf(s[k], zv.x, q0);
            q1 = fmaf(s[k], zv.y, q1);
            q2 = fmaf(s[k], zv.z, q2);
            q3 = fmaf(s[k], zv.w, q3);
        }
        float o0 = sb2v[0], o1 = sb2v[1], o2 = sb2v[2], o3 = sb2v[3];
#pragma unroll
        for (int j = 0; j < 32; j++) {
            float4 wc = *(const float4*)&sw1[j * 4];
            float tt = sb1[j];
            tt = fmaf(q0, wc.x, tt);
            tt = fmaf(q1, wc.y, tt);
            tt = fmaf(q2, wc.z, tt);
            tt = fmaf(q3, wc.w, tt);
            tt = siluf(tt);
            float4 wr = *(const float4*)&sw2[j * 4];
            o0 = fmaf(tt, wr.x, o0);
            o1 = fmaf(tt, wr.y, o1);
            o2 = fmaf(tt, wr.z, o2);
            o3 = fmaf(tt, wr.w, o3);
        }
        *(float4*)(out + ((size_t)b * NODES + n) * 4) = make_float4(o0, o1, o2, o3);
    }
}

// ---------------- launch ----------------
extern "C" void kernel_launch(void* const* d_in, const int* in_sizes, int n_in,
                              void* d_out, int out_size) {
    const float* x      = (const float*)d_in[0];
    const float* pos    = (const float*)d_in[1];
    const void*  ei     = d_in[2];
    const void*  batch  = d_in[3];
    const float* enc_w1 = (const float*)d_in[4];
    const float* enc_b1 = (const float*)d_in[5];
    const float* enc_w2 = (const float*)d_in[6];
    const float* enc_b2 = (const float*)d_in[7];
    const float* pool_w = (const float*)d_in[8];
    const float* pool_b = (const float*)d_in[9];
    const float* toz_w  = (const float*)d_in[10];
    const float* toz_b  = (const float*)d_in[11];
    const float* dec_w1 = (const float*)d_in[12];
    const float* dec_b1 = (const float*)d_in[13];
    const float* dec_w2 = (const float*)d_in[14];
    const float* dec_b2 = (const float*)d_in[15];
    float* out = (float*)d_out;

    k_prep_a<<<3125, 128>>>(ei);                             // 1
    k_scan<<<SCANB, 1024>>>(ei, batch, pos);                 // 2 (+batch+pos4)
    k_scatsrc<<<3125, 256>>>(ei, x, enc_w1);                 // 3 (2 edges/thread)
    k_main<<<1184, 256>>>(x, enc_w1, enc_b1, enc_w2, enc_b2, // 4  <- profiled slot
                          pool_w, pool_b);
    k_pool<<<256, 256>>>(toz_w, toz_b);                      // 5 (+fused z)
    k_dec<<<(NODES + 127) / 128, 128>>>(dec_w1, dec_b1, dec_w2, dec_b2, out);  // 6
}